// round 14
// baseline (speedup 1.0000x reference)
#include <cuda_runtime.h>
#include <cuda_bf16.h>
#include <math.h>

#define NN 100000
#define NE 1600000
#define HID 64
#define DN 128
#define NT (NE / 128)        // 12500 edge tiles
#define PGRID 296            // persistent grid: 148 SMs x 2 CTAs

// ---------------- scratch (device globals; no allocations allowed) ----------
__device__ __align__(16) float g_node_proj[(size_t)NN * HID];   // 25.6 MB
__device__ __align__(16) float g_h_new[(size_t)NN * HID];       // 25.6 MB
// fragment-packed weights: [16 ksteps][32 lanes][20 floats (16 used, 4 pad)]
__device__ __align__(16) float g_WedgeF[16 * 32 * 20];
__device__ __align__(16) float g_WnodeF[16 * 32 * 20];
__device__ __align__(16) float g_BcatF[4 * 16 * 32 * 20];
__device__ float g_bias[256];

// ---------------- helpers ---------------------------------------------------
__device__ __forceinline__ void mma8(float c[4], unsigned a0, unsigned a1,
                                     unsigned a2, unsigned a3,
                                     unsigned b0, unsigned b1) {
    asm volatile(
        "mma.sync.aligned.m16n8k8.row.col.f32.tf32.tf32.f32 "
        "{%0,%1,%2,%3}, {%4,%5,%6,%7}, {%8,%9}, {%0,%1,%2,%3};"
        : "+f"(c[0]), "+f"(c[1]), "+f"(c[2]), "+f"(c[3])
        : "r"(a0), "r"(a1), "r"(a2), "r"(a3), "r"(b0), "r"(b1));
}

__device__ __forceinline__ unsigned smaddr(const void* p) {
    return (unsigned)__cvta_generic_to_shared(p);
}
__device__ __forceinline__ void cpa16(unsigned s, const void* g) {
    asm volatile("cp.async.cg.shared.global [%0], [%1], 16;" :: "r"(s), "l"(g));
}
// evict-first variant for read-once streams (protects L2 working set)
__device__ __forceinline__ void cpa16_ef(unsigned s, const void* g) {
    asm volatile(
        "{\n\t.reg .b64 pol;\n\t"
        "createpolicy.fractional.L2::evict_first.b64 pol, 1.0;\n\t"
        "cp.async.cg.shared.global.L2::cache_hint [%0], [%1], 16, pol;\n\t}"
        :: "r"(s), "l"(g));
}
// zero-fills when src_sz == 0 (row guard for tail blocks)
__device__ __forceinline__ void cpa16z(unsigned s, const void* g, int src_sz) {
    asm volatile("cp.async.cg.shared.global [%0], [%1], 16, %2;"
                 :: "r"(s), "l"(g), "r"(src_sz));
}
__device__ __forceinline__ void cpa16z_ef(unsigned s, const void* g, int src_sz) {
    asm volatile(
        "{\n\t.reg .b64 pol;\n\t"
        "createpolicy.fractional.L2::evict_first.b64 pol, 1.0;\n\t"
        "cp.async.cg.shared.global.L2::cache_hint [%0], [%1], 16, %2, pol;\n\t}"
        :: "r"(s), "l"(g), "r"(src_sz));
}
__device__ __forceinline__ void cpa_commit() {
    asm volatile("cp.async.commit_group;");
}
template <int N>
__device__ __forceinline__ void cpa_wait() {
    asm volatile("cp.async.wait_group %0;" :: "n"(N));
}

#define PADA 132   // A tile row stride (floats): conflict-free a-frag LDS
#define WF_FLOATS (16 * 32 * 20)                 // 10240 floats = 40960 B
#define SMEM_FLOATS (128 * PADA + WF_FLOATS)     // 27136 floats = 108544 B
#define SMEM_GG (128 * PADA + 2 * WF_FLOATS)     // gatesgru: A + 2 W buffers

// GEMM body: C[128x64] = A[128x128] * W^T. A raw fp32 in smem (MMA truncates
// to tf32), W fragment-packed: per kstep each lane reads 4 float4s (LDS.128,
// conflict-free: 80B lane slots spread across all banks).
#define GEMM_BODY(sA, sWf, acc)                                                \
    {                                                                          \
        const float* wfl = (sWf) + lane * 20;                                  \
        _Pragma("unroll")                                                      \
        for (int kk = 0; kk < 16; kk++) {                                      \
            float4 f0 = *(const float4*)(wfl + kk * 640);                      \
            float4 f1 = *(const float4*)(wfl + kk * 640 + 4);                  \
            float4 f2 = *(const float4*)(wfl + kk * 640 + 8);                  \
            float4 f3 = *(const float4*)(wfl + kk * 640 + 12);                 \
            unsigned a0 = __float_as_uint((sA)[r1 * PADA + kk * 8 + q4]);      \
            unsigned a1 = __float_as_uint((sA)[(r1 + 8) * PADA + kk * 8 + q4]);\
            unsigned a2 = __float_as_uint((sA)[r1 * PADA + kk * 8 + q4 + 4]);  \
            unsigned a3 = __float_as_uint((sA)[(r1 + 8) * PADA + kk * 8 + q4 + 4]); \
            mma8(acc[0], a0, a1, a2, a3, __float_as_uint(f0.x), __float_as_uint(f0.y)); \
            mma8(acc[1], a0, a1, a2, a3, __float_as_uint(f0.z), __float_as_uint(f0.w)); \
            mma8(acc[2], a0, a1, a2, a3, __float_as_uint(f1.x), __float_as_uint(f1.y)); \
            mma8(acc[3], a0, a1, a2, a3, __float_as_uint(f1.z), __float_as_uint(f1.w)); \
            mma8(acc[4], a0, a1, a2, a3, __float_as_uint(f2.x), __float_as_uint(f2.y)); \
            mma8(acc[5], a0, a1, a2, a3, __float_as_uint(f2.z), __float_as_uint(f2.w)); \
            mma8(acc[6], a0, a1, a2, a3, __float_as_uint(f3.x), __float_as_uint(f3.y)); \
            mma8(acc[7], a0, a1, a2, a3, __float_as_uint(f3.z), __float_as_uint(f3.w)); \
        }                                                                      \
    }

// ---------------- K0a: zero h_new -------------------------------------------
__global__ void zero_kernel() {
    size_t i = (size_t)blockIdx.x * blockDim.x + threadIdx.x;
    if (i < (size_t)NN * 16) ((float4*)g_h_new)[i] = make_float4(0.f, 0.f, 0.f, 0.f);
}

// ---------------- K0b: pack fragment-ordered weights + bias -----------------
__device__ __forceinline__ float bcat_val(const float* W_ih, const float* W_hh,
                                          int n, int k) {
    int g = n >> 6, c = n & 63;
    if (g == 0) return (k < 64) ? W_ih[c * 64 + k] : W_hh[c * 64 + (k - 64)];
    if (g == 1) return (k < 64) ? W_ih[(64 + c) * 64 + k] : W_hh[(64 + c) * 64 + (k - 64)];
    if (g == 2) return (k < 64) ? W_ih[(128 + c) * 64 + k] : 0.f;
    return (k >= 64) ? W_hh[(128 + c) * 64 + (k - 64)] : 0.f;
}

__global__ void pack_kernel(const float* __restrict__ W_edge,
                            const float* __restrict__ W_node,
                            const float* __restrict__ W_ih,
                            const float* __restrict__ W_hh,
                            const float* __restrict__ b_ih,
                            const float* __restrict__ b_hh) {
    int i = blockIdx.x * blockDim.x + threadIdx.x;
    if (i < WF_FLOATS) {
        int kk = i / 640, rem = i % 640, lane = rem / 20, t = rem % 20;
        float ve = 0.f, vn = 0.f;
        if (t < 16) {
            int q = lane >> 2, q4 = lane & 3, j = t >> 1, wh = t & 1;
            int n = j * 8 + q, k = kk * 8 + q4 + 4 * wh;
            ve = W_edge[n * 128 + k];
            vn = W_node[n * 128 + k];
        }
        g_WedgeF[i] = ve;
        g_WnodeF[i] = vn;
    }
    if (i < 4 * WF_FLOATS) {
        int nc = i / WF_FLOATS, r = i % WF_FLOATS;
        int kk = r / 640, rem = r % 640, lane = rem / 20, t = rem % 20;
        float v = 0.f;
        if (t < 16) {
            int q = lane >> 2, q4 = lane & 3, j = t >> 1, wh = t & 1;
            int n = nc * 64 + j * 8 + q, k = kk * 8 + q4 + 4 * wh;
            v = bcat_val(W_ih, W_hh, n, k);
        }
        g_BcatF[i] = v;
    }
    if (i < 256) {
        int g = i >> 6, c = i & 63;
        float b;
        if (g == 0)      b = b_ih[c] + b_hh[c];
        else if (g == 1) b = b_ih[64 + c] + b_hh[64 + c];
        else if (g == 2) b = b_ih[128 + c];
        else             b = b_hh[128 + c];
        g_bias[i] = b;
    }
}

// ---------------- K1: node_proj = node_feats @ W_node^T ---------------------
__global__ __launch_bounds__(256, 2) void nodeproj_kernel(
    const float* __restrict__ node_feats) {
    extern __shared__ float sm[];
    float* sA = sm;
    float* sWf = sm + 128 * PADA;
    int tid = threadIdx.x;
    size_t n0 = (size_t)blockIdx.x * 128;
    unsigned sA_u = smaddr(sA), sWf_u = smaddr(sWf);

    for (int i = tid; i < 4096; i += 256) {
        int r = i >> 5, c = i & 31;
        bool ok = (n0 + (size_t)r < NN);
        size_t rr = ok ? (n0 + (size_t)r) : (size_t)(NN - 1);   // in-bounds addr always
        cpa16z_ef(sA_u + r * (PADA * 4) + c * 16,
                  (const char*)(node_feats + rr * DN) + c * 16, ok ? 16 : 0);
    }
    for (int i = tid; i < 2560; i += 256)
        cpa16(sWf_u + i * 16, (const char*)g_WnodeF + (size_t)i * 16);
    cpa_commit();
    cpa_wait<0>();
    __syncthreads();

    int lane = tid & 31, warp = tid >> 5;
    int q = lane >> 2, q4 = lane & 3;
    int r1 = warp * 16 + q;
    float acc[8][4];
#pragma unroll
    for (int j = 0; j < 8; j++) acc[j][0] = acc[j][1] = acc[j][2] = acc[j][3] = 0.f;

    GEMM_BODY(sA, sWf, acc);

#pragma unroll
    for (int half = 0; half < 2; half++) {
        size_t r = n0 + r1 + half * 8;
        if (r < NN) {
#pragma unroll
            for (int j = 0; j < 8; j++) {
                float2 o = make_float2(acc[j][half * 2], acc[j][half * 2 + 1]);
                *(float2*)&g_node_proj[r * 64 + j * 8 + 2 * q4] = o;
            }
        }
    }
}

// ---------------- K2: persistent pipelined edge kernel ----------------------
// Per tile: GEMM on staged A, P gathered as registers before GEMM (scoreboard-
// covered), next tile's A/indices cp.async'd right after GEMM, H gathered in
// epilogue (covered by softmax), scatter via float2 atomics. W loaded once.
__global__ __launch_bounds__(256, 2) void edge_kernel(
    const float* __restrict__ edge_feats,
    const int* __restrict__ src, const int* __restrict__ dst,
    const float* __restrict__ node_hidden) {
    extern __shared__ float sm[];
    float* sA = sm;                    // 128 x PADA
    float* sWf = sm + 128 * PADA;      // fragment-packed W (persistent)
    __shared__ __align__(16) int s_src[2][128], s_dst[2][128];

    int tid = threadIdx.x;
    unsigned sA_u = smaddr(sA), sWf_u = smaddr(sWf);
    unsigned ssrc_u = smaddr(s_src), sdst_u = smaddr(s_dst);

    int lane = tid & 31, warp = tid >> 5;
    int q = lane >> 2, q4 = lane & 3;
    int r1 = warp * 16 + q;

    // prologue: W (once) + first tile A + indices, one group
    for (int i = tid; i < 2560; i += 256)
        cpa16(sWf_u + i * 16, (const char*)g_WedgeF + (size_t)i * 16);
    int t0 = blockIdx.x;
    {
        const char* gA = (const char*)(edge_feats + (size_t)t0 * 128 * DN);
        for (int i = tid; i < 4096; i += 256) {
            int r = i >> 5, c = i & 31;
            cpa16_ef(sA_u + r * (PADA * 4) + c * 16, gA + (size_t)i * 16);
        }
        if (tid < 32)
            cpa16(ssrc_u + tid * 16, (const char*)(src + (size_t)t0 * 128) + tid * 16);
        else if (tid < 64)
            cpa16(sdst_u + (tid - 32) * 16, (const char*)(dst + (size_t)t0 * 128) + (tid - 32) * 16);
    }
    cpa_commit();

    int p = 0;
    for (int t = t0; t < NT; t += PGRID, p ^= 1) {
        cpa_wait<0>();          // A[t], idx[t] resident (mostly pre-arrived)
        __syncthreads();

        // P gather into registers (fragment-aligned float2), covered by GEMM
        float2 pl[2][8];
        {
            int s0 = s_src[p][r1], s1 = s_src[p][r1 + 8];
            const float2* P0 = (const float2*)(g_node_proj + (size_t)s0 * 64) + q4;
            const float2* P1 = (const float2*)(g_node_proj + (size_t)s1 * 64) + q4;
#pragma unroll
            for (int j = 0; j < 8; j++) { pl[0][j] = P0[j * 4]; pl[1][j] = P1[j * 4]; }
        }

        float acc[8][4];
#pragma unroll
        for (int j = 0; j < 8; j++) acc[j][0] = acc[j][1] = acc[j][2] = acc[j][3] = 0.f;

        GEMM_BODY(sA, sWf, acc);
        __syncthreads();        // sA fully consumed

        // stage next tile (A into sA, indices into parity^1) — hides DRAM
        // latency behind the epilogue below + next iteration's top
        int tn = t + PGRID;
        if (tn < NT) {
            const char* gA = (const char*)(edge_feats + (size_t)tn * 128 * DN);
            for (int i = tid; i < 4096; i += 256) {
                int r = i >> 5, c = i & 31;
                cpa16_ef(sA_u + r * (PADA * 4) + c * 16, gA + (size_t)i * 16);
            }
            int pn = p ^ 1;
            if (tid < 32)
                cpa16(ssrc_u + pn * 512 + tid * 16,
                      (const char*)(src + (size_t)tn * 128) + tid * 16);
            else if (tid < 64)
                cpa16(sdst_u + pn * 512 + (tid - 32) * 16,
                      (const char*)(dst + (size_t)tn * 128) + (tid - 32) * 16);
            cpa_commit();
        }

        // epilogue: add proj, row softmax over 64, m = hidden*alpha, scatter
#pragma unroll
        for (int half = 0; half < 2; half++) {
            int r = r1 + half * 8;
            int s = s_src[p][r];
            int d = s_dst[p][r];
            float v[16];
#pragma unroll
            for (int j = 0; j < 8; j++) {
                v[2 * j]     = acc[j][half * 2]     + pl[half][j].x;
                v[2 * j + 1] = acc[j][half * 2 + 1] + pl[half][j].y;
            }
            // H gather (L2-hot), issued early so softmax math covers latency
            float2 hl[8];
            const float2* H = (const float2*)(node_hidden + (size_t)s * 64) + q4;
#pragma unroll
            for (int j = 0; j < 8; j++) hl[j] = H[j * 4];

            float mx = v[0];
#pragma unroll
            for (int tt = 1; tt < 16; tt++) mx = fmaxf(mx, v[tt]);
            mx = fmaxf(mx, __shfl_xor_sync(0xffffffffu, mx, 1));
            mx = fmaxf(mx, __shfl_xor_sync(0xffffffffu, mx, 2));
            float ssum = 0.f;
#pragma unroll
            for (int tt = 0; tt < 16; tt++) { v[tt] = __expf(v[tt] - mx); ssum += v[tt]; }
            ssum += __shfl_xor_sync(0xffffffffu, ssum, 1);
            ssum += __shfl_xor_sync(0xffffffffu, ssum, 2);
            float inv = 1.f / ssum;
            float* hrow = g_h_new + (size_t)d * 64;
#pragma unroll
            for (int j = 0; j < 8; j++) {
                float2 m2;
                m2.x = v[2 * j]     * inv * hl[j].x;
                m2.y = v[2 * j + 1] * inv * hl[j].y;
                atomicAdd((float2*)(hrow + j * 8 + 2 * q4), m2);
            }
        }
    }
}

// ---------------- K3: fused gates GEMM + GRU epilogue (W double-buffered) ---
__global__ __launch_bounds__(256) void gatesgru_kernel(
    const float* __restrict__ node_hidden, float* __restrict__ out) {
    extern __shared__ float sm[];
    float* sA = sm;
    float* sW0 = sm + 128 * PADA;
    float* sW1 = sW0 + WF_FLOATS;
    __shared__ float sbias[256];
    int tid = threadIdx.x;
    size_t n0 = (size_t)blockIdx.x * 128;
    unsigned sA_u = smaddr(sA), sW0_u = smaddr(sW0), sW1_u = smaddr(sW1);

    sbias[tid] = g_bias[tid];

    for (int i = tid; i < 4096; i += 256) {
        int r = i >> 5, c = i & 31;
        bool ok = (n0 + (size_t)r < NN);
        size_t rr = ok ? (n0 + (size_t)r) : (size_t)(NN - 1);
        const char* ptr = (c < 16)
            ? (const char*)(g_h_new + rr * 64) + c * 16
            : (const char*)(node_hidden + rr * 64) + (c - 16) * 16;
        cpa16z(sA_u + r * (PADA * 4) + c * 16, ptr, ok ? 16 : 0);
    }
    for (int i = tid; i < 2560; i += 256) {
        cpa16(sW0_u + i * 16, (const char*)g_BcatF + (size_t)i * 16);
        cpa16(sW1_u + i * 16, (const char*)(g_BcatF + WF_FLOATS) + (size_t)i * 16);
    }
    cpa_commit();
    cpa_wait<0>();
    __syncthreads();

    int lane = tid & 31, warp = tid >> 5;
    int q = lane >> 2, q4 = lane & 3;
    int r1 = warp * 16 + q;

    float rg[8][4], zg[8][4], pi[8][4];

    // chunk 0: r gate (buf0); stream W2 into buf0 afterwards
    {
        float acc0[8][4];
#pragma unroll
        for (int j = 0; j < 8; j++) acc0[j][0] = acc0[j][1] = acc0[j][2] = acc0[j][3] = 0.f;
        GEMM_BODY(sA, sW0, acc0);
        __syncthreads();
        const char* gW = (const char*)(g_BcatF + (size_t)2 * WF_FLOATS);
        for (int i = tid; i < 2560; i += 256) cpa16(sW0_u + i * 16, gW + (size_t)i * 16);
        cpa_commit();
#pragma unroll
        for (int j = 0; j < 8; j++)
#pragma unroll
            for (int k = 0; k < 4; k++) {
                int col = j * 8 + 2 * q4 + (k & 1);
                rg[j][k] = 1.f / (1.f + __expf(-(acc0[j][k] + sbias[col])));
            }
    }
    // chunk 1: z gate (buf1); stream W3 into buf1 afterwards
    {
        float acc1[8][4];
#pragma unroll
        for (int j = 0; j < 8; j++) acc1[j][0] = acc1[j][1] = acc1[j][2] = acc1[j][3] = 0.f;
        GEMM_BODY(sA, sW1, acc1);
        __syncthreads();
        const char* gW = (const char*)(g_BcatF + (size_t)3 * WF_FLOATS);
        for (int i = tid; i < 2560; i += 256) cpa16(sW1_u + i * 16, gW + (size_t)i * 16);
        cpa_commit();
#pragma unroll
        for (int j = 0; j < 8; j++)
#pragma unroll
            for (int k = 0; k < 4; k++) {
                int col = j * 8 + 2 * q4 + (k & 1);
                zg[j][k] = 1.f / (1.f + __expf(-(acc1[j][k] + sbias[64 + col])));
            }
    }
    // chunk 2: i_n pre-activation (buf0 = W2; allow W3 still in flight)
    {
        cpa_wait<1>();
        __syncthreads();
        float acc2[8][4];
#pragma unroll
        for (int j = 0; j < 8; j++) acc2[j][0] = acc2[j][1] = acc2[j][2] = acc2[j][3] = 0.f;
        GEMM_BODY(sA, sW0, acc2);
#pragma unroll
        for (int j = 0; j < 8; j++)
#pragma unroll
            for (int k = 0; k < 4; k++) {
                int col = j * 8 + 2 * q4 + (k & 1);
                pi[j][k] = acc2[j][k] + sbias[128 + col];
            }
    }
    // chunk 3: h_n (buf1 = W3) + final GRU combine
    {
        cpa_wait<0>();
        __syncthreads();
        float acc3[8][4];
#pragma unroll
        for (int j = 0; j < 8; j++) acc3[j][0] = acc3[j][1] = acc3[j][2] = acc3[j][3] = 0.f;
        GEMM_BODY(sA, sW1, acc3);

#pragma unroll
        for (int half = 0; half < 2; half++) {
            int row = r1 + half * 8;
            size_t grow = n0 + (size_t)row;
            if (grow < NN) {
#pragma unroll
                for (int j = 0; j < 8; j++) {
                    int col = j * 8 + 2 * q4;
                    float2 o;
#pragma unroll
                    for (int s = 0; s < 2; s++) {
                        int k = half * 2 + s;
                        float ph = acc3[j][k] + sbias[192 + col + s];
                        float n = tanhf(pi[j][k] + rg[j][k] * ph);
                        float h = sA[row * PADA + 64 + col + s];
                        float v = (1.f - zg[j][k]) * n + zg[j][k] * h;
                        if (s == 0) o.x = v; else o.y = v;
                    }
                    *(float2*)&out[grow * 64 + col] = o;
                }
            }
        }
    }
}

// ---------------- launch -----------------------------------------------------
extern "C" void kernel_launch(void* const* d_in, const int* in_sizes, int n_in,
                              void* d_out, int out_size) {
    const float* node_feats  = (const float*)d_in[0];
    const float* edge_feats  = (const float*)d_in[1];
    const float* node_hidden = (const float*)d_in[2];
    const int*   src         = (const int*)d_in[3];
    const int*   dst         = (const int*)d_in[4];
    const float* W_edge      = (const float*)d_in[5];
    const float* W_node      = (const float*)d_in[6];
    const float* W_ih        = (const float*)d_in[7];
    const float* W_hh        = (const float*)d_in[8];
    const float* b_ih        = (const float*)d_in[9];
    const float* b_hh        = (const float*)d_in[10];
    float* out = (float*)d_out;

    const int smem   = SMEM_FLOATS * 4;   // 108544 bytes (nodeproj/edge)
    const int smemGG = SMEM_GG * 4;       // 149504 bytes (gatesgru)
    cudaFuncSetAttribute(nodeproj_kernel, cudaFuncAttributeMaxDynamicSharedMemorySize, smem);
    cudaFuncSetAttribute(edge_kernel,     cudaFuncAttributeMaxDynamicSharedMemorySize, smem);
    cudaFuncSetAttribute(gatesgru_kernel, cudaFuncAttributeMaxDynamicSharedMemorySize, smemGG);

    zero_kernel<<<(NN * 16 + 255) / 256, 256>>>();
    pack_kernel<<<(4 * WF_FLOATS + 255) / 256, 256>>>(W_edge, W_node, W_ih, W_hh, b_ih, b_hh);
    nodeproj_kernel<<<(NN + 127) / 128, 256, smem>>>(node_feats);
    edge_kernel<<<PGRID, 256, smem>>>(edge_feats, src, dst, node_hidden);
    gatesgru_kernel<<<(NN + 127) / 128, 256, smemGG>>>(node_hidden, out);
}